// round 1
// baseline (speedup 1.0000x reference)
#include <cuda_runtime.h>
#include <math.h>

// Problem constants
#define Bsz     131072
#define Dd      128
#define Hh      128
#define Ll      4
#define TR      64           // rows per tile
#define THREADS 256
#define NBLK    304          // persistent-ish grid (2 per SM on 152 SMs)
#define NTILES  (Bsz / TR)   // 2048
#define SHP     132          // shared pitch (floats), padded
#define LN_EPS  1e-5f

// -------- static device scratch (no runtime allocation allowed) --------
__device__ float g_WinT[128 * 128];        // W_in^T  [k][j] = W_in[j][k]
__device__ float g_WoutT[128 * 128];       // W_out^T
__device__ float g_WlT[4 * 128 * 128];     // Wl[i]^T
__device__ float g_emb[4 * 128];           // sin(t*fw+fb)
__device__ float g_u[(size_t)NBLK * 4 * TR * 128];  // saved pre-softplus per CTA

// ---------------- prep: transposes + time embedding ----------------
__global__ void prep_kernel(const float* __restrict__ t,
                            const float* __restrict__ W_in,
                            const float* __restrict__ fw,
                            const float* __restrict__ fb,
                            const float* __restrict__ Wl,
                            const float* __restrict__ W_out) {
    int idx = blockIdx.x * blockDim.x + threadIdx.x;
    if (idx < 128 * 128) {
        int k = idx >> 7, j = idx & 127;
        g_WinT[idx] = W_in[j * 128 + k];
    } else if (idx < 2 * 128 * 128) {
        int r = idx - 128 * 128;
        int k = r >> 7, j = r & 127;
        g_WoutT[r] = W_out[j * 128 + k];
    } else if (idx < 6 * 128 * 128) {
        int r = idx - 2 * 128 * 128;
        int l = r >> 14;
        int within = r & 16383;
        int k = within >> 7, j = within & 127;
        g_WlT[r] = Wl[l * 16384 + j * 128 + k];
    } else if (idx < 6 * 128 * 128 + 4 * 128) {
        int r = idx - 6 * 128 * 128;
        g_emb[r] = sinf(t[0] * fw[r] + fb[r]);
    }
}

// ---------------- helpers ----------------
__device__ __forceinline__ float softplusf_(float u) {
    // matches jax.nn.softplus: max(u,0) + log1p(exp(-|u|))
    return fmaxf(u, 0.f) + log1pf(expf(-fabsf(u)));
}
__device__ __forceinline__ float sigmoidf_(float u) {
    return 1.f / (1.f + expf(-u));
}
__device__ __forceinline__ float f4c(float4 v, int kk) {
    return kk == 0 ? v.x : kk == 1 ? v.y : kk == 2 ? v.z : v.w;
}

// load TR x 128 rows (global, row-major) into padded shared
__device__ __forceinline__ void load_rows(float* dst, const float* __restrict__ src, int tid) {
#pragma unroll
    for (int it = 0; it < (TR * 32) / THREADS; it++) {
        int i = tid + it * THREADS;           // float4 index
        int row = i >> 5, c4 = (i & 31) << 2;
        *(float4*)(dst + row * SHP + c4) = *(const float4*)(src + row * 128 + c4);
    }
}
// load 128 x 128 weight (global, contiguous) into padded shared
__device__ __forceinline__ void load_w(float* dst, const float* __restrict__ src, int tid) {
#pragma unroll
    for (int it = 0; it < (128 * 32) / THREADS; it++) {
        int i = tid + it * THREADS;
        int row = i >> 5, c4 = (i & 31) << 2;
        *(float4*)(dst + row * SHP + c4) = *(const float4*)(src + row * 128 + c4);
    }
}

// acc[r][j] = sum_k sA[(r0+r)][k] * sW[k][j0+j]
__device__ __forceinline__ void mm_tile(const float* __restrict__ sA,
                                        const float* __restrict__ sW,
                                        float acc[4][8], int r0, int j0) {
#pragma unroll
    for (int r = 0; r < 4; r++)
#pragma unroll
        for (int j = 0; j < 8; j++) acc[r][j] = 0.f;

#pragma unroll 2
    for (int k = 0; k < 128; k += 4) {
        float4 a4[4];
#pragma unroll
        for (int r = 0; r < 4; r++)
            a4[r] = *(const float4*)(sA + (r0 + r) * SHP + k);
#pragma unroll
        for (int kk = 0; kk < 4; kk++) {
            float4 w0 = *(const float4*)(sW + (k + kk) * SHP + j0);
            float4 w1 = *(const float4*)(sW + (k + kk) * SHP + j0 + 4);
            float wb[8] = {w0.x, w0.y, w0.z, w0.w, w1.x, w1.y, w1.z, w1.w};
#pragma unroll
            for (int r = 0; r < 4; r++) {
                float av = f4c(a4[r], kk);
#pragma unroll
                for (int j = 0; j < 8; j++)
                    acc[r][j] = fmaf(av, wb[j], acc[r][j]);
            }
        }
    }
}

__device__ __forceinline__ void writeback(float* sh_h, float acc[4][8],
                                          const float* __restrict__ bias,
                                          int r0, int j0) {
    float bj[8];
#pragma unroll
    for (int j = 0; j < 8; j++) bj[j] = bias ? bias[j0 + j] : 0.f;
#pragma unroll
    for (int r = 0; r < 4; r++) {
        float4 v0, v1;
        v0.x = acc[r][0] + bj[0]; v0.y = acc[r][1] + bj[1];
        v0.z = acc[r][2] + bj[2]; v0.w = acc[r][3] + bj[3];
        v1.x = acc[r][4] + bj[4]; v1.y = acc[r][5] + bj[5];
        v1.z = acc[r][6] + bj[6]; v1.w = acc[r][7] + bj[7];
        *(float4*)(sh_h + (r0 + r) * SHP + j0)     = v0;
        *(float4*)(sh_h + (r0 + r) * SHP + j0 + 4) = v1;
    }
}

// ---------------- main fused kernel ----------------
extern __shared__ float smem[];

__global__ void __launch_bounds__(THREADS, 2)
clnf_main(const float* __restrict__ p, const float* __restrict__ w,
          const float* __restrict__ W_in, const float* __restrict__ b_in,
          const float* __restrict__ gamma, const float* __restrict__ beta,
          const float* __restrict__ Wl, const float* __restrict__ bl,
          const float* __restrict__ W_out, const float* __restrict__ b_out,
          float* __restrict__ out) {
    float* sh_h  = smem;                         // TR x SHP
    float* sh_w  = smem + TR * SHP;              // 128 x SHP
    float* sh_mu = smem + TR * SHP + 128 * SHP;  // 4 * TR
    float* sh_rs = sh_mu + 4 * TR;               // 4 * TR

    const int tid  = threadIdx.x;
    const int jg   = tid & 15,  rg = tid >> 4;
    const int j0   = jg * 8,    r0 = rg * 4;
    const int warp = tid >> 5,  lane = tid & 31;

    float* my_u = g_u + (size_t)blockIdx.x * (4 * TR * 128);
    float* dwo  = out + (size_t)Bsz * 128;

    const int c = lane * 4;   // column base for elementwise phases

    for (int tile = blockIdx.x; tile < NTILES; tile += NBLK) {
        const size_t row0 = (size_t)tile * TR;
        float acc[4][8];

        // ---------- forward: in-projection ----------
        load_rows(sh_h, p + row0 * 128, tid);
        load_w(sh_w, g_WinT, tid);
        __syncthreads();
        mm_tile(sh_h, sh_w, acc, r0, j0);
        __syncthreads();
        writeback(sh_h, acc, b_in, r0, j0);
        __syncthreads();

        // ---------- forward: 4 layers ----------
        for (int i = 0; i < Ll; i++) {
            // elementwise: emb add, save u, softplus, LN   (warp-exclusive rows)
            {
                float4 e  = *(const float4*)(g_emb + i * 128 + c);
                float4 ga = *(const float4*)(gamma + i * 128 + c);
                float4 be = *(const float4*)(beta  + i * 128 + c);
#pragma unroll
                for (int rr = 0; rr < 8; rr++) {
                    int row = warp * 8 + rr;
                    float4 h = *(float4*)(sh_h + row * SHP + c);
                    float u0 = h.x + e.x, u1 = h.y + e.y, u2 = h.z + e.z, u3 = h.w + e.w;
                    *(float4*)(my_u + ((i * TR + row) << 7) + c) =
                        make_float4(u0, u1, u2, u3);
                    float s0 = softplusf_(u0), s1 = softplusf_(u1);
                    float s2 = softplusf_(u2), s3 = softplusf_(u3);
                    float sum = s0 + s1 + s2 + s3;
#pragma unroll
                    for (int o = 16; o; o >>= 1) sum += __shfl_xor_sync(0xffffffffu, sum, o);
                    float mu = sum * (1.f / 128.f);
                    float d0 = s0 - mu, d1 = s1 - mu, d2 = s2 - mu, d3 = s3 - mu;
                    float sq = d0 * d0 + d1 * d1 + d2 * d2 + d3 * d3;
#pragma unroll
                    for (int o = 16; o; o >>= 1) sq += __shfl_xor_sync(0xffffffffu, sq, o);
                    float var = sq * (1.f / 128.f);
                    float rs  = rsqrtf(var + LN_EPS);
                    if (lane == 0) { sh_mu[i * TR + row] = mu; sh_rs[i * TR + row] = rs; }
                    float4 y;
                    y.x = d0 * rs * ga.x + be.x;
                    y.y = d1 * rs * ga.y + be.y;
                    y.z = d2 * rs * ga.z + be.z;
                    y.w = d3 * rs * ga.w + be.w;
                    *(float4*)(sh_h + row * SHP + c) = y;
                }
            }
            load_w(sh_w, g_WlT + i * 16384, tid);
            __syncthreads();
            mm_tile(sh_h, sh_w, acc, r0, j0);
            __syncthreads();
            writeback(sh_h, acc, bl + i * 128, r0, j0);
            __syncthreads();
        }

        // ---------- forward: out-projection -> dp ----------
        load_w(sh_w, g_WoutT, tid);
        __syncthreads();
        mm_tile(sh_h, sh_w, acc, r0, j0);
        {
            float bj[8];
#pragma unroll
            for (int j = 0; j < 8; j++) bj[j] = b_out[j0 + j];
#pragma unroll
            for (int r = 0; r < 4; r++) {
                float4 v0, v1;
                v0.x = acc[r][0] + bj[0]; v0.y = acc[r][1] + bj[1];
                v0.z = acc[r][2] + bj[2]; v0.w = acc[r][3] + bj[3];
                v1.x = acc[r][4] + bj[4]; v1.y = acc[r][5] + bj[5];
                v1.z = acc[r][6] + bj[6]; v1.w = acc[r][7] + bj[7];
                size_t o = (row0 + r0 + r) * 128 + j0;
                *(float4*)(out + o)     = v0;
                *(float4*)(out + o + 4) = v1;
            }
        }
        __syncthreads();

        // ---------- backward: g = w @ W_out ----------
        load_rows(sh_h, w + row0 * 128, tid);
        load_w(sh_w, W_out, tid);
        __syncthreads();
        mm_tile(sh_h, sh_w, acc, r0, j0);
        __syncthreads();
        writeback(sh_h, acc, nullptr, r0, j0);
        __syncthreads();

        // ---------- backward: 4 layers (reverse) ----------
        for (int i = Ll - 1; i >= 0; i--) {
            load_w(sh_w, Wl + i * 16384, tid);   // original layout = transposed matmul
            __syncthreads();
            mm_tile(sh_h, sh_w, acc, r0, j0);    // gy = g @ Wl[i]
            __syncthreads();
            writeback(sh_h, acc, nullptr, r0, j0);
            __syncthreads();
            // elementwise backward: LN bwd + softplus bwd (warp-exclusive rows)
            {
                float4 ga = *(const float4*)(gamma + i * 128 + c);
#pragma unroll
                for (int rr = 0; rr < 8; rr++) {
                    int row = warp * 8 + rr;
                    float mu = sh_mu[i * TR + row];
                    float rs = sh_rs[i * TR + row];
                    float4 gy = *(float4*)(sh_h + row * SHP + c);
                    float4 u  = *(const float4*)(my_u + ((i * TR + row) << 7) + c);
                    float s0 = softplusf_(u.x), s1 = softplusf_(u.y);
                    float s2 = softplusf_(u.z), s3 = softplusf_(u.w);
                    float x0 = (s0 - mu) * rs, x1 = (s1 - mu) * rs;
                    float x2 = (s2 - mu) * rs, x3 = (s3 - mu) * rs;
                    float t0 = gy.x * ga.x, t1 = gy.y * ga.y;
                    float t2 = gy.z * ga.z, t3 = gy.w * ga.w;
                    float m1 = t0 + t1 + t2 + t3;
                    float m2 = t0 * x0 + t1 * x1 + t2 * x2 + t3 * x3;
#pragma unroll
                    for (int o = 16; o; o >>= 1) {
                        m1 += __shfl_xor_sync(0xffffffffu, m1, o);
                        m2 += __shfl_xor_sync(0xffffffffu, m2, o);
                    }
                    m1 *= (1.f / 128.f);
                    m2 *= (1.f / 128.f);
                    float4 gn;
                    gn.x = rs * (t0 - m1 - x0 * m2) * sigmoidf_(u.x);
                    gn.y = rs * (t1 - m1 - x1 * m2) * sigmoidf_(u.y);
                    gn.z = rs * (t2 - m1 - x2 * m2) * sigmoidf_(u.z);
                    gn.w = rs * (t3 - m1 - x3 * m2) * sigmoidf_(u.w);
                    *(float4*)(sh_h + row * SHP + c) = gn;
                }
            }
            __syncthreads();
        }

        // ---------- backward: dw = -(g @ W_in) ----------
        load_w(sh_w, W_in, tid);
        __syncthreads();
        mm_tile(sh_h, sh_w, acc, r0, j0);
#pragma unroll
        for (int r = 0; r < 4; r++) {
            float4 v0, v1;
            v0.x = -acc[r][0]; v0.y = -acc[r][1]; v0.z = -acc[r][2]; v0.w = -acc[r][3];
            v1.x = -acc[r][4]; v1.y = -acc[r][5]; v1.z = -acc[r][6]; v1.w = -acc[r][7];
            size_t o = (row0 + r0 + r) * 128 + j0;
            *(float4*)(dwo + o)     = v0;
            *(float4*)(dwo + o + 4) = v1;
        }
        __syncthreads();   // protect sh_h/sh_w before next tile iteration
    }
}

// ---------------- launch ----------------
extern "C" void kernel_launch(void* const* d_in, const int* in_sizes, int n_in,
                              void* d_out, int out_size) {
    const float* t     = (const float*)d_in[0];
    const float* p     = (const float*)d_in[1];
    const float* w     = (const float*)d_in[2];
    const float* W_in  = (const float*)d_in[3];
    const float* b_in  = (const float*)d_in[4];
    const float* fw    = (const float*)d_in[5];
    const float* fb    = (const float*)d_in[6];
    const float* gamma = (const float*)d_in[7];
    const float* beta  = (const float*)d_in[8];
    const float* Wl    = (const float*)d_in[9];
    const float* bl    = (const float*)d_in[10];
    const float* W_out = (const float*)d_in[11];
    const float* b_out = (const float*)d_in[12];
    float* out = (float*)d_out;

    const int smem_bytes = (TR * SHP + 128 * SHP + 8 * TR) * sizeof(float); // 103424
    cudaFuncSetAttribute(clnf_main, cudaFuncAttributeMaxDynamicSharedMemorySize,
                         smem_bytes);

    int prep_total = 6 * 128 * 128 + 4 * 128;
    prep_kernel<<<(prep_total + 255) / 256, 256>>>(t, W_in, fw, fb, Wl, W_out);
    clnf_main<<<NBLK, THREADS, smem_bytes>>>(p, w, W_in, b_in, gamma, beta,
                                             Wl, bl, W_out, b_out, out);
}

// round 2
// speedup vs baseline: 1.1668x; 1.1668x over previous
#include <cuda_runtime.h>
#include <math.h>

// Problem constants
#define Bsz     131072
#define Dd      128
#define Hh      128
#define Ll      4
#define TR      128          // rows per tile
#define THREADS 256
#define NBLK    152          // persistent grid: 1 CTA/SM on GB300 (152 SMs)
#define NTILES  (Bsz / TR)   // 1024
#define PH      132          // pitch of activation tile (floats, 16B-aligned rows)
#define PW      130          // pitch of k-major weight tile (bank stride 2 -> conflict-free)
#define LN_EPS  1e-5f

typedef unsigned long long ull;

// -------- static device scratch (no runtime allocation allowed) --------
__device__ float g_WinT[128 * 128];        // W_in^T  [j][k] = W_in[k][j]
__device__ float g_WoutT[128 * 128];       // W_out^T
__device__ float g_WlT[4 * 128 * 128];     // Wl[i]^T
__device__ float g_emb[4 * 128];           // sin(t*fw+fb)
__device__ float g_s[(size_t)NBLK * 4 * TR * 128];  // saved softplus(u) per CTA

// ---------------- prep: transposes + time embedding ----------------
__global__ void prep_kernel(const float* __restrict__ t,
                            const float* __restrict__ W_in,
                            const float* __restrict__ fw,
                            const float* __restrict__ fb,
                            const float* __restrict__ Wl,
                            const float* __restrict__ W_out) {
    int idx = blockIdx.x * blockDim.x + threadIdx.x;
    if (idx < 128 * 128) {
        int a = idx >> 7, b = idx & 127;
        g_WinT[idx] = W_in[b * 128 + a];          // g_WinT[j][k] = W_in[k][j]
    } else if (idx < 2 * 128 * 128) {
        int r = idx - 128 * 128;
        int a = r >> 7, b = r & 127;
        g_WoutT[r] = W_out[b * 128 + a];
    } else if (idx < 6 * 128 * 128) {
        int r = idx - 2 * 128 * 128;
        int l = r >> 14;
        int within = r & 16383;
        int a = within >> 7, b = within & 127;
        g_WlT[r] = Wl[l * 16384 + b * 128 + a];
    } else if (idx < 6 * 128 * 128 + 4 * 128) {
        int r = idx - 6 * 128 * 128;
        g_emb[r] = sinf(t[0] * fw[r] + fb[r]);
    }
}

// ---------------- helpers ----------------
__device__ __forceinline__ float softplusf_(float u) {
    return fmaxf(u, 0.f) + log1pf(expf(-fabsf(u)));
}
__device__ __forceinline__ float lo32(ull v) { return __uint_as_float((unsigned)v); }
__device__ __forceinline__ float hi32(ull v) { return __uint_as_float((unsigned)(v >> 32)); }

// load TR x 128 rows (global, row-major) into padded shared (pitch PH)
__device__ __forceinline__ void load_rows(float* dst, const float* __restrict__ src, int tid) {
#pragma unroll
    for (int it = 0; it < (TR * 32) / THREADS; it++) {
        int i = tid + it * THREADS;           // float4 index
        int row = i >> 5, c4 = (i & 31) << 2;
        *(float4*)(dst + row * PH + c4) = *(const float4*)(src + row * 128 + c4);
    }
}
// load 128x128 weight (contiguous) into k-major shared with pitch PW (8B stores)
__device__ __forceinline__ void load_w(float* dst, const float* __restrict__ src, int tid) {
#pragma unroll
    for (int it = 0; it < (128 * 64) / THREADS; it++) {
        int i = tid + it * THREADS;           // float2 index
        int row = i >> 6, c2 = (i & 63) << 1;
        *(float2*)(dst + row * PW + c2) = *(const float2*)(src + row * 128 + c2);
    }
}

// 8x8 micro-tile GEMM with packed f32x2 FMA; acc halves hold even/odd-k partials
__device__ __forceinline__ void mm8x8(const float* __restrict__ sA,
                                      const float* __restrict__ sW,
                                      ull acc[8][8], int r0, int jg) {
#pragma unroll
    for (int r = 0; r < 8; r++)
#pragma unroll
        for (int c = 0; c < 8; c++) acc[r][c] = 0ull;

    const float* aB = sA + r0 * PH;
    const float* wB = sW + jg * PW;
#pragma unroll 2
    for (int k = 0; k < 128; k += 2) {
        ull a2[8], w2[8];
#pragma unroll
        for (int r = 0; r < 8; r++)
            a2[r] = *(const ull*)(aB + r * PH + k);
#pragma unroll
        for (int c = 0; c < 8; c++)
            w2[c] = *(const ull*)(wB + c * (16 * PW) + k);
#pragma unroll
        for (int r = 0; r < 8; r++)
#pragma unroll
            for (int c = 0; c < 8; c++)
                asm("fma.rn.f32x2 %0, %1, %2, %0;"
                    : "+l"(acc[r][c]) : "l"(a2[r]), "l"(w2[c]));
    }
}

// write acc (+bias) back into shared activation tile
__device__ __forceinline__ void wb_shared(float* sh_h, ull acc[8][8],
                                          const float* __restrict__ bias,
                                          int r0, int jg) {
    float bj[8];
#pragma unroll
    for (int c = 0; c < 8; c++) bj[c] = bias ? bias[jg + 16 * c] : 0.f;
#pragma unroll
    for (int r = 0; r < 8; r++)
#pragma unroll
        for (int c = 0; c < 8; c++)
            sh_h[(r0 + r) * PH + jg + 16 * c] =
                lo32(acc[r][c]) + hi32(acc[r][c]) + bj[c];
}

// ---------------- main fused kernel ----------------
extern __shared__ float smem[];

__global__ void __launch_bounds__(THREADS, 1)
clnf_main(const float* __restrict__ p, const float* __restrict__ w,
          const float* __restrict__ W_in, const float* __restrict__ b_in,
          const float* __restrict__ gamma, const float* __restrict__ beta,
          const float* __restrict__ Wl, const float* __restrict__ bl,
          const float* __restrict__ W_out, const float* __restrict__ b_out,
          float* __restrict__ out) {
    float* sh_h  = smem;                          // TR x PH
    float* sh_w  = smem + TR * PH;                // 128 x PW (k-major)
    float* sh_mu = sh_w + 128 * PW;               // 4 * TR
    float* sh_rs = sh_mu + 4 * TR;                // 4 * TR

    const int tid  = threadIdx.x;
    const int jg   = tid & 15;        // col base; thread cols = jg + 16*c
    const int rg   = tid >> 4;        // row group
    const int r0   = rg * 8;
    const int warp = tid >> 5, lane = tid & 31;
    const int c    = lane * 4;        // column base for elementwise phases

    float* my_s = g_s + (size_t)blockIdx.x * (4 * TR * 128);
    float* dwo  = out + (size_t)Bsz * 128;

    for (int tile = blockIdx.x; tile < NTILES; tile += NBLK) {
        const size_t row0 = (size_t)tile * TR;
        ull acc[8][8];

        // ---------- forward: in-projection ----------
        load_rows(sh_h, p + row0 * 128, tid);
        load_w(sh_w, W_in, tid);                  // fwd: sWt[j][k] = W_in[j][k]
        __syncthreads();
        mm8x8(sh_h, sh_w, acc, r0, jg);
        __syncthreads();
        wb_shared(sh_h, acc, b_in, r0, jg);
        __syncthreads();

        // ---------- forward: 4 layers ----------
        for (int i = 0; i < Ll; i++) {
            // elementwise: emb add, softplus, save s, LN   (warp handles 16 rows)
            {
                float4 e  = *(const float4*)(g_emb + i * 128 + c);
                float4 ga = *(const float4*)(gamma + i * 128 + c);
                float4 be = *(const float4*)(beta  + i * 128 + c);
#pragma unroll
                for (int rr = 0; rr < 16; rr++) {
                    int row = warp * 16 + rr;
                    float4 h = *(float4*)(sh_h + row * PH + c);
                    float s0 = softplusf_(h.x + e.x), s1 = softplusf_(h.y + e.y);
                    float s2 = softplusf_(h.z + e.z), s3 = softplusf_(h.w + e.w);
                    *(float4*)(my_s + ((i * TR + row) << 7) + c) =
                        make_float4(s0, s1, s2, s3);
                    float sum = s0 + s1 + s2 + s3;
#pragma unroll
                    for (int o = 16; o; o >>= 1) sum += __shfl_xor_sync(0xffffffffu, sum, o);
                    float mu = sum * (1.f / 128.f);
                    float d0 = s0 - mu, d1 = s1 - mu, d2 = s2 - mu, d3 = s3 - mu;
                    float sq = d0 * d0 + d1 * d1 + d2 * d2 + d3 * d3;
#pragma unroll
                    for (int o = 16; o; o >>= 1) sq += __shfl_xor_sync(0xffffffffu, sq, o);
                    float rs = rsqrtf(sq * (1.f / 128.f) + LN_EPS);
                    if (lane == 0) { sh_mu[i * TR + row] = mu; sh_rs[i * TR + row] = rs; }
                    float4 y;
                    y.x = d0 * rs * ga.x + be.x;
                    y.y = d1 * rs * ga.y + be.y;
                    y.z = d2 * rs * ga.z + be.z;
                    y.w = d3 * rs * ga.w + be.w;
                    *(float4*)(sh_h + row * PH + c) = y;
                }
            }
            load_w(sh_w, Wl + i * 16384, tid);    // fwd: sWt[j][k] = Wl[i][j][k]
            __syncthreads();
            mm8x8(sh_h, sh_w, acc, r0, jg);
            __syncthreads();
            wb_shared(sh_h, acc, bl + i * 128, r0, jg);
            __syncthreads();
        }

        // ---------- forward: out-projection -> dp (direct global) ----------
        load_w(sh_w, W_out, tid);
        __syncthreads();
        mm8x8(sh_h, sh_w, acc, r0, jg);
        {
            float bj[8];
#pragma unroll
            for (int cc = 0; cc < 8; cc++) bj[cc] = b_out[jg + 16 * cc];
#pragma unroll
            for (int r = 0; r < 8; r++)
#pragma unroll
                for (int cc = 0; cc < 8; cc++)
                    out[(row0 + r0 + r) * 128 + jg + 16 * cc] =
                        lo32(acc[r][cc]) + hi32(acc[r][cc]) + bj[cc];
        }
        __syncthreads();

        // ---------- backward: g = w @ W_out  (needs W_out^T in k-major) ----------
        load_rows(sh_h, w + row0 * 128, tid);
        load_w(sh_w, g_WoutT, tid);
        __syncthreads();
        mm8x8(sh_h, sh_w, acc, r0, jg);
        __syncthreads();
        wb_shared(sh_h, acc, nullptr, r0, jg);
        __syncthreads();

        // ---------- backward: 4 layers (reverse) ----------
        for (int i = Ll - 1; i >= 0; i--) {
            load_w(sh_w, g_WlT + i * 16384, tid); // bwd: sWt[j][k] = Wl[i][k][j]
            __syncthreads();
            mm8x8(sh_h, sh_w, acc, r0, jg);       // gy = g @ Wl[i]
            __syncthreads();
            wb_shared(sh_h, acc, nullptr, r0, jg);
            __syncthreads();
            // elementwise backward: LN bwd + softplus bwd
            {
                float4 ga = *(const float4*)(gamma + i * 128 + c);
#pragma unroll
                for (int rr = 0; rr < 16; rr++) {
                    int row = warp * 16 + rr;
                    float mu = sh_mu[i * TR + row];
                    float rs = sh_rs[i * TR + row];
                    float4 gy = *(float4*)(sh_h + row * PH + c);
                    float4 s  = *(const float4*)(my_s + ((i * TR + row) << 7) + c);
                    float x0 = (s.x - mu) * rs, x1 = (s.y - mu) * rs;
                    float x2 = (s.z - mu) * rs, x3 = (s.w - mu) * rs;
                    float t0 = gy.x * ga.x, t1 = gy.y * ga.y;
                    float t2 = gy.z * ga.z, t3 = gy.w * ga.w;
                    float m1 = t0 + t1 + t2 + t3;
                    float m2 = t0 * x0 + t1 * x1 + t2 * x2 + t3 * x3;
#pragma unroll
                    for (int o = 16; o; o >>= 1) {
                        m1 += __shfl_xor_sync(0xffffffffu, m1, o);
                        m2 += __shfl_xor_sync(0xffffffffu, m2, o);
                    }
                    m1 *= (1.f / 128.f);
                    m2 *= (1.f / 128.f);
                    float4 gn;   // sigmoid(u) = 1 - exp(-softplus(u))
                    gn.x = rs * (t0 - m1 - x0 * m2) * (1.f - expf(-s.x));
                    gn.y = rs * (t1 - m1 - x1 * m2) * (1.f - expf(-s.y));
                    gn.z = rs * (t2 - m1 - x2 * m2) * (1.f - expf(-s.z));
                    gn.w = rs * (t3 - m1 - x3 * m2) * (1.f - expf(-s.w));
                    *(float4*)(sh_h + row * PH + c) = gn;
                }
            }
            __syncthreads();
        }

        // ---------- backward: dw = -(g @ W_in)  (needs W_in^T) ----------
        load_w(sh_w, g_WinT, tid);
        __syncthreads();
        mm8x8(sh_h, sh_w, acc, r0, jg);
#pragma unroll
        for (int r = 0; r < 8; r++)
#pragma unroll
            for (int cc = 0; cc < 8; cc++)
                dwo[(row0 + r0 + r) * 128 + jg + 16 * cc] =
                    -(lo32(acc[r][cc]) + hi32(acc[r][cc]));
        __syncthreads();   // protect sh_h/sh_w before next tile iteration
    }
}

// ---------------- launch ----------------
extern "C" void kernel_launch(void* const* d_in, const int* in_sizes, int n_in,
                              void* d_out, int out_size) {
    const float* t     = (const float*)d_in[0];
    const float* p     = (const float*)d_in[1];
    const float* w     = (const float*)d_in[2];
    const float* W_in  = (const float*)d_in[3];
    const float* b_in  = (const float*)d_in[4];
    const float* fw    = (const float*)d_in[5];
    const float* fb    = (const float*)d_in[6];
    const float* gamma = (const float*)d_in[7];
    const float* beta  = (const float*)d_in[8];
    const float* Wl    = (const float*)d_in[9];
    const float* bl    = (const float*)d_in[10];
    const float* W_out = (const float*)d_in[11];
    const float* b_out = (const float*)d_in[12];
    float* out = (float*)d_out;

    const int smem_bytes = (TR * PH + 128 * PW + 8 * TR) * sizeof(float); // ~138 KB
    cudaFuncSetAttribute(clnf_main, cudaFuncAttributeMaxDynamicSharedMemorySize,
                         smem_bytes);

    int prep_total = 6 * 128 * 128 + 4 * 128;
    prep_kernel<<<(prep_total + 255) / 256, 256>>>(t, W_in, fw, fb, Wl, W_out);
    clnf_main<<<NBLK, THREADS, smem_bytes>>>(p, w, W_in, b_in, gamma, beta,
                                             Wl, bl, W_out, b_out, out);
}

// round 7
// speedup vs baseline: 2.5095x; 2.1506x over previous
#include <cuda_runtime.h>
#include <cuda_bf16.h>
#include <math.h>
#include <stdint.h>

// ---------------- problem constants ----------------
#define Bsz     131072
#define TR      128
#define THREADS 256
#define NBLK    152
#define NTILES  (Bsz / TR)     // 1024
#define LN_EPS  1e-5f
#define PK      136            // bf16 pitch (elems) -> 272B rows, ldmatrix conflict-free
#define PKB     272
#define IMG_HALF (128 * PK)           // 17408 elems (one hi or lo image)
#define IMG_ELEMS (2 * 128 * PK)      // 34816 elems = 69632 B per weight image

// SMEM byte layout
#define SM_A_HI 0
#define SM_A_LO 34816
#define SM_B0   69632
#define SM_B1   139264
#define SM_CB   208896                 // 6*128 floats
#define SM_CEMB (SM_CB + 3072)
#define SM_CGAM (SM_CEMB + 2048)
#define SM_CBET (SM_CGAM + 2048)
#define SM_TOTAL (SM_CBET + 2048)      // 218112 B

// ---------------- static device scratch ----------------
__device__ __align__(16) __nv_bfloat16 g_Bimg[12 * IMG_ELEMS];
__device__ float g_emb[512];
__device__ float g_s[(size_t)NBLK * 4 * TR * 128];   // saved softplus per CTA

// ---------------- prep: padded bf16 hi/lo weight images + emb ----------------
__global__ void prep_kernel(const float* __restrict__ t,
                            const float* __restrict__ W_in,
                            const float* __restrict__ fw,
                            const float* __restrict__ fb,
                            const float* __restrict__ Wl,
                            const float* __restrict__ W_out) {
    int idx = blockIdx.x * blockDim.x + threadIdx.x;
    if (idx < 12 * 16384) {
        int m = idx >> 14;
        int kn = idx & 16383;
        int k = kn >> 7, n = kn & 127;   // image element B[k][n]
        float v;
        if      (m == 0)  v = W_in[n * 128 + k];                  // W_in^T
        else if (m <= 4)  v = Wl[(m - 1) * 16384 + n * 128 + k];  // Wl[i]^T
        else if (m == 5)  v = W_out[n * 128 + k];                 // W_out^T
        else if (m == 6)  v = W_out[k * 128 + n];                 // W_out
        else if (m <= 10) v = Wl[(m - 7) * 16384 + k * 128 + n];  // Wl[i]
        else              v = W_in[k * 128 + n];                  // W_in
        __nv_bfloat16 h = __float2bfloat16(v);
        __nv_bfloat16 l = __float2bfloat16(v - __bfloat162float(h));
        g_Bimg[m * IMG_ELEMS + k * PK + n] = h;
        g_Bimg[m * IMG_ELEMS + IMG_HALF + k * PK + n] = l;
    } else if (idx < 12 * 16384 + 512) {
        int j = idx - 12 * 16384;
        g_emb[j] = sinf(t[0] * fw[j] + fb[j]);
    }
}

// ---------------- PTX helpers ----------------
__device__ __forceinline__ uint32_t smem_u32(const void* p) {
    uint32_t a;
    asm("{ .reg .u64 t; cvta.to.shared.u64 t, %1; cvt.u32.u64 %0, t; }" : "=r"(a) : "l"(p));
    return a;
}
__device__ __forceinline__ void ldsm4(uint32_t r[4], uint32_t addr) {
    asm volatile("ldmatrix.sync.aligned.m8n8.x4.shared.b16 {%0,%1,%2,%3}, [%4];"
                 : "=r"(r[0]), "=r"(r[1]), "=r"(r[2]), "=r"(r[3]) : "r"(addr));
}
__device__ __forceinline__ void ldsm2t(uint32_t r[2], uint32_t addr) {
    asm volatile("ldmatrix.sync.aligned.m8n8.x2.trans.shared.b16 {%0,%1}, [%2];"
                 : "=r"(r[0]), "=r"(r[1]) : "r"(addr));
}
__device__ __forceinline__ void mma16816(float c[4], const uint32_t a[4], const uint32_t b[2]) {
    asm volatile("mma.sync.aligned.m16n8k16.row.col.f32.bf16.bf16.f32 "
                 "{%0,%1,%2,%3},{%4,%5,%6,%7},{%8,%9},{%0,%1,%2,%3};"
                 : "+f"(c[0]), "+f"(c[1]), "+f"(c[2]), "+f"(c[3])
                 : "r"(a[0]), "r"(a[1]), "r"(a[2]), "r"(a[3]), "r"(b[0]), "r"(b[1]));
}
// pack {x,y} -> bf16x2 hi + residual bf16x2 lo
__device__ __forceinline__ void pack2(float x, float y, uint32_t& hi, uint32_t& lo) {
    asm("cvt.rn.bf16x2.f32 %0, %1, %2;" : "=r"(hi) : "f"(y), "f"(x));
    float hx = __uint_as_float(hi << 16);
    float hy = __uint_as_float(hi & 0xffff0000u);
    asm("cvt.rn.bf16x2.f32 %0, %1, %2;" : "=r"(lo) : "f"(y - hy), "f"(x - hx));
}
__device__ __forceinline__ float qreduce(float v) {   // sum over quad (lanes xor 1,2)
    v += __shfl_xor_sync(0xffffffffu, v, 1);
    v += __shfl_xor_sync(0xffffffffu, v, 2);
    return v;
}
__device__ __forceinline__ float softplusf_(float u) {
    return fmaxf(u, 0.f) + log1pf(__expf(-fabsf(u)));
}
__device__ __forceinline__ int mat_for(int g) {
    return (g <= 6) ? g : (g == 11 ? 11 : 17 - g);
}

// 69632B contiguous copy global -> smem (all 256 threads)
__device__ __forceinline__ void copyB(char* dst, const __nv_bfloat16* src, int tid) {
    const uint4* s = (const uint4*)src;
    uint4* d = (uint4*)dst;
#pragma unroll
    for (int it = 0; it < 17; it++) d[tid + it * 256] = s[tid + it * 256];
}

// one 128x128x128 GEMM product-triple: acc += Ah*Bh + Al*Bh + Ah*Bl (warp rows)
__device__ __forceinline__ void do_gemm(float acc[16][4], uint32_t aH, uint32_t aL,
                                        uint32_t bH, uint32_t bL, int warp, int lane) {
    __syncwarp();
#pragma unroll
    for (int nt = 0; nt < 16; nt++)
#pragma unroll
        for (int q = 0; q < 4; q++) acc[nt][q] = 0.f;

    const uint32_t a_off = (uint32_t)(warp * 16 + (lane & 15)) * PKB + ((lane >> 4) * 8) * 2;
    const uint32_t b_off = (uint32_t)(lane & 15) * PKB;
#pragma unroll
    for (int ks = 0; ks < 8; ks++) {
        uint32_t ah[4], al[4];
        ldsm4(ah, aH + a_off + ks * 32);
        ldsm4(al, aL + a_off + ks * 32);
#pragma unroll
        for (int nt = 0; nt < 16; nt++) {
            uint32_t bh[2], bl2[2];
            uint32_t bo = (uint32_t)(ks * 16) * PKB + b_off + nt * 16;
            ldsm2t(bh, bH + bo);
            mma16816(acc[nt], ah, bh);
            mma16816(acc[nt], al, bh);
            ldsm2t(bl2, bL + bo);
            mma16816(acc[nt], ah, bl2);
        }
    }
}

// ---------------- main kernel ----------------
extern __shared__ __align__(16) char smem[];

__global__ void __launch_bounds__(THREADS, 1)
clnf_main(const float* __restrict__ p, const float* __restrict__ w,
          const float* __restrict__ b_in, const float* __restrict__ gamma,
          const float* __restrict__ beta, const float* __restrict__ bl,
          const float* __restrict__ b_out, float* __restrict__ out) {
    const int tid  = threadIdx.x;
    const int warp = tid >> 5, lane = tid & 31;
    const int qr   = lane >> 2, qc = lane & 3;
    const int rwA  = warp * 16 + qr;          // fragment row (rb=0)
    const int rwB  = rwA + 8;                 // fragment row (rb=1)

    const uint32_t sbase = smem_u32(smem);
    const uint32_t saH = sbase + SM_A_HI, saL = sbase + SM_A_LO;
    float* cb   = (float*)(smem + SM_CB);
    float* cemb = (float*)(smem + SM_CEMB);
    float* cgam = (float*)(smem + SM_CGAM);
    float* cbet = (float*)(smem + SM_CBET);
    float* dwo  = out + (size_t)Bsz * 128;

    // consts -> SMEM
    if (tid < 128) { cb[tid] = b_in[tid]; cb[640 + tid] = b_out[tid]; }
#pragma unroll
    for (int i = 0; i < 2; i++) {
        int j = tid + i * 256;
        cb[128 + j] = bl[j];
        cemb[j] = g_emb[j];
        cgam[j] = gamma[j];
        cbet[j] = beta[j];
    }
    // preload B image 0 into buf0
    copyB(smem + SM_B0, g_Bimg, tid);
    __syncthreads();

    const int colb = qc * 2;                  // thread col base within n-tile
    float mus[4][2], rss[4][2];
    float acc[16][4];

    for (int tile = blockIdx.x; tile < NTILES; tile += NBLK) {
        const size_t row0 = (size_t)tile * TR;

        // ---- initial A = p rows (warp-local fragment-layout pack) ----
#pragma unroll
        for (int rb = 0; rb < 2; rb++) {
            int rw = rb ? rwB : rwA;
            const float* src = p + (row0 + rw) * 128 + colb;
#pragma unroll
            for (int nt = 0; nt < 16; nt++) {
                float2 v = *(const float2*)(src + nt * 8);
                uint32_t hi, lo;
                pack2(v.x, v.y, hi, lo);
                uint32_t boff = (uint32_t)rw * PKB + nt * 16 + qc * 4;
                *(uint32_t*)(smem + SM_A_HI + boff) = hi;
                *(uint32_t*)(smem + SM_A_LO + boff) = lo;
            }
        }

        for (int g = 0; g < 12; g++) {
            uint32_t bbuf = sbase + ((g & 1) ? SM_B1 : SM_B0);
            do_gemm(acc, saH, saL, bbuf, bbuf + 34816, warp, lane);

            // prefetch next B into the other buffer (reads overlap epilogue)
            {
                int gn = (g == 11) ? 0 : g + 1;
                copyB(smem + ((g & 1) ? SM_B0 : SM_B1),
                      g_Bimg + (size_t)mat_for(gn) * IMG_ELEMS, tid);
            }

            // ---- epilogue (warp-local) ----
            if (g <= 4) {                      // + bias (b_in, bl0..3)
                const float* bp = cb + g * 128 + colb;
#pragma unroll
                for (int nt = 0; nt < 16; nt++) {
                    float2 b2 = *(const float2*)(bp + nt * 8);
#pragma unroll
                    for (int rb = 0; rb < 2; rb++) {
                        acc[nt][2 * rb]     += b2.x;
                        acc[nt][2 * rb + 1] += b2.y;
                    }
                }
            }
            if (g <= 3) {                      // fwd layer g: emb, softplus, LN
                const float* eb = cemb + g * 128 + colb;
                const float* ga = cgam + g * 128 + colb;
                const float* be = cbet + g * 128 + colb;
#pragma unroll
                for (int rb = 0; rb < 2; rb++) {
                    int rw = rb ? rwB : rwA;
                    float sum = 0.f;
#pragma unroll
                    for (int nt = 0; nt < 16; nt++) {
                        float2 e2 = *(const float2*)(eb + nt * 8);
                        float s0 = softplusf_(acc[nt][2 * rb]     + e2.x);
                        float s1 = softplusf_(acc[nt][2 * rb + 1] + e2.y);
                        acc[nt][2 * rb] = s0; acc[nt][2 * rb + 1] = s1;
                        sum += s0 + s1;
                    }
                    float mu = qreduce(sum) * (1.f / 128.f);
                    float ssq = 0.f;
#pragma unroll
                    for (int nt = 0; nt < 16; nt++) {
                        float d0 = acc[nt][2 * rb] - mu, d1 = acc[nt][2 * rb + 1] - mu;
                        ssq += d0 * d0 + d1 * d1;
                    }
                    float rs = rsqrtf(qreduce(ssq) * (1.f / 128.f) + LN_EPS);
                    mus[g][rb] = mu; rss[g][rb] = rs;
                    float* sp = g_s + (((size_t)blockIdx.x * 4 + g) * 128 + rw) * 128 + colb;
#pragma unroll
                    for (int nt = 0; nt < 16; nt++)
                        *(float2*)(sp + nt * 8) =
                            make_float2(acc[nt][2 * rb], acc[nt][2 * rb + 1]);
#pragma unroll
                    for (int nt = 0; nt < 16; nt++) {
                        float2 g2 = *(const float2*)(ga + nt * 8);
                        float2 t2 = *(const float2*)(be + nt * 8);
                        float y0 = (acc[nt][2 * rb] - mu) * rs * g2.x + t2.x;
                        float y1 = (acc[nt][2 * rb + 1] - mu) * rs * g2.y + t2.y;
                        uint32_t hi, lo;
                        pack2(y0, y1, hi, lo);
                        uint32_t boff = (uint32_t)rw * PKB + nt * 16 + qc * 4;
                        *(uint32_t*)(smem + SM_A_HI + boff) = hi;
                        *(uint32_t*)(smem + SM_A_LO + boff) = lo;
                    }
                }
            } else if (g == 4 || g == 6) {     // pack result straight into A
#pragma unroll
                for (int rb = 0; rb < 2; rb++) {
                    int rw = rb ? rwB : rwA;
#pragma unroll
                    for (int nt = 0; nt < 16; nt++) {
                        uint32_t hi, lo;
                        pack2(acc[nt][2 * rb], acc[nt][2 * rb + 1], hi, lo);
                        uint32_t boff = (uint32_t)rw * PKB + nt * 16 + qc * 4;
                        *(uint32_t*)(smem + SM_A_HI + boff) = hi;
                        *(uint32_t*)(smem + SM_A_LO + boff) = lo;
                    }
                }
            } else if (g == 5) {               // dp out (+b_out); load w rows into A
                const float* bp = cb + 640 + colb;
#pragma unroll
                for (int rb = 0; rb < 2; rb++) {
                    int rw = rb ? rwB : rwA;
                    float* dst = out + (row0 + rw) * 128 + colb;
#pragma unroll
                    for (int nt = 0; nt < 16; nt++) {
                        float2 b2 = *(const float2*)(bp + nt * 8);
                        *(float2*)(dst + nt * 8) =
                            make_float2(acc[nt][2 * rb] + b2.x, acc[nt][2 * rb + 1] + b2.y);
                    }
                    const float* src = w + (row0 + rw) * 128 + colb;
#pragma unroll
                    for (int nt = 0; nt < 16; nt++) {
                        float2 v = *(const float2*)(src + nt * 8);
                        uint32_t hi, lo;
                        pack2(v.x, v.y, hi, lo);
                        uint32_t boff = (uint32_t)rw * PKB + nt * 16 + qc * 4;
                        *(uint32_t*)(smem + SM_A_HI + boff) = hi;
                        *(uint32_t*)(smem + SM_A_LO + boff) = lo;
                    }
                }
            } else if (g >= 7 && g <= 10) {    // bwd layer l = 10-g
                int l = 10 - g;
                const float* ga = cgam + l * 128 + colb;
#pragma unroll
                for (int rb = 0; rb < 2; rb++) {
                    int rw = rb ? rwB : rwA;
                    float mu = mus[l][rb], rs = rss[l][rb];
                    const float* sp = g_s +
                        (((size_t)blockIdx.x * 4 + l) * 128 + rw) * 128 + colb;
                    float sv[32];
#pragma unroll
                    for (int nt = 0; nt < 16; nt++) {
                        float2 s2 = *(const float2*)(sp + nt * 8);
                        sv[2 * nt] = s2.x; sv[2 * nt + 1] = s2.y;
                    }
                    float m1 = 0.f, m2 = 0.f;
#pragma unroll
                    for (int nt = 0; nt < 16; nt++) {
                        float2 g2 = *(const float2*)(ga + nt * 8);
                        float t0 = acc[nt][2 * rb] * g2.x;
                        float t1 = acc[nt][2 * rb + 1] * g2.y;
                        m1 += t0 + t1;
                        m2 += t0 * ((sv[2 * nt] - mu) * rs) +
                              t1 * ((sv[2 * nt + 1] - mu) * rs);
                    }
                    m1 = qreduce(m1) * (1.f / 128.f);
                    m2 = qreduce(m2) * (1.f / 128.f);
#pragma unroll
                    for (int nt = 0; nt < 16; nt++) {
                        float2 g2 = *(const float2*)(ga + nt * 8);
                        float t0 = acc[nt][2 * rb] * g2.x;
                        float t1 = acc[nt][2 * rb + 1] * g2.y;
                        float x0 = (sv[2 * nt] - mu) * rs;
                        float x1 = (sv[2 * nt + 1] - mu) * rs;
                        float n0 = rs * (t0 - m1 - x0 * m2) * (1.f - __expf(-sv[2 * nt]));
                        float n1 = rs * (t1 - m1 - x1 * m2) * (1.f - __expf(-sv[2 * nt + 1]));
                        uint32_t hi, lo;
                        pack2(n0, n1, hi, lo);
                        uint32_t boff = (uint32_t)rw * PKB + nt * 16 + qc * 4;
                        *(uint32_t*)(smem + SM_A_HI + boff) = hi;
                        *(uint32_t*)(smem + SM_A_LO + boff) = lo;
                    }
                }
            } else {                           // g == 11: dw = -D
#pragma unroll
                for (int rb = 0; rb < 2; rb++) {
                    int rw = rb ? rwB : rwA;
                    float* dst = dwo + (row0 + rw) * 128 + colb;
#pragma unroll
                    for (int nt = 0; nt < 16; nt++)
                        *(float2*)(dst + nt * 8) =
                            make_float2(-acc[nt][2 * rb], -acc[nt][2 * rb + 1]);
                }
            }
            __syncthreads();   // B double-buffer handoff
        }
    }
}

// ---------------- launch ----------------
extern "C" void kernel_launch(void* const* d_in, const int* in_sizes, int n_in,
                              void* d_out, int out_size) {
    const float* t     = (const float*)d_in[0];
    const float* p     = (const float*)d_in[1];
    const float* w     = (const float*)d_in[2];
    const float* W_in  = (const float*)d_in[3];
    const float* b_in  = (const float*)d_in[4];
    const float* fw    = (const float*)d_in[5];
    const float* fb    = (const float*)d_in[6];
    const float* gamma = (const float*)d_in[7];
    const float* beta  = (const float*)d_in[8];
    const float* Wl    = (const float*)d_in[9];
    const float* bl    = (const float*)d_in[10];
    const float* W_out = (const float*)d_in[11];
    const float* b_out = (const float*)d_in[12];
    float* out = (float*)d_out;

    cudaFuncSetAttribute(clnf_main, cudaFuncAttributeMaxDynamicSharedMemorySize,
                         SM_TOTAL);

    int prep_total = 12 * 16384 + 512;
    prep_kernel<<<(prep_total + 255) / 256, 256>>>(t, W_in, fw, fb, Wl, W_out);
    clnf_main<<<NBLK, THREADS, SM_TOTAL>>>(p, w, b_in, gamma, beta, bl, b_out, out);
}

// round 10
// speedup vs baseline: 3.3422x; 1.3318x over previous
#include <cuda_runtime.h>
#include <cuda_bf16.h>
#include <math.h>
#include <stdint.h>

// ---------------- problem constants ----------------
#define Bsz     131072
#define TR      128
#define THREADS 256
#define NBLK    152
#define NTILES  (Bsz / TR)     // 1024
#define LN_EPS  1e-5f
#define PK      136            // bf16 pitch (elems) -> 272B rows, ldmatrix conflict-free
#define PKB     272
#define IMG_HALF   (128 * PK)            // elems in one (hi or lo) image
#define IMG_HALF_B (IMG_HALF * 2)        // 34816 bytes
#define IMG_ELEMS  (2 * 128 * PK)        // 34816 elems = 69632 B per weight image

// SMEM byte layout: two B buffers + constants
#define SM_B0   0
#define SM_B1   69632
#define SM_CB   139264                 // 6*128 floats
#define SM_CEMB (SM_CB + 3072)
#define SM_CGAM (SM_CEMB + 2048)
#define SM_CBET (SM_CGAM + 2048)
#define SM_TOTAL (SM_CBET + 2048)      // 147456 B

// ---------------- static device scratch ----------------
__device__ __align__(16) __nv_bfloat16 g_Bimg[12 * IMG_ELEMS];
__device__ float g_emb[512];
__device__ float g_s[(size_t)NBLK * 4 * TR * 128];   // saved softplus per CTA

// ---------------- prep: padded bf16 hi/lo weight images + emb ----------------
__global__ void prep_kernel(const float* __restrict__ t,
                            const float* __restrict__ W_in,
                            const float* __restrict__ fw,
                            const float* __restrict__ fb,
                            const float* __restrict__ Wl,
                            const float* __restrict__ W_out) {
    int idx = blockIdx.x * blockDim.x + threadIdx.x;
    if (idx < 12 * 16384) {
        int m = idx >> 14;
        int kn = idx & 16383;
        int k = kn >> 7, n = kn & 127;   // image element B[k][n]
        float v;
        if      (m == 0)  v = W_in[n * 128 + k];                  // W_in^T
        else if (m <= 4)  v = Wl[(m - 1) * 16384 + n * 128 + k];  // Wl[i]^T
        else if (m == 5)  v = W_out[n * 128 + k];                 // W_out^T
        else if (m == 6)  v = W_out[k * 128 + n];                 // W_out
        else if (m <= 10) v = Wl[(m - 7) * 16384 + k * 128 + n];  // Wl[i]
        else              v = W_in[k * 128 + n];                  // W_in
        __nv_bfloat16 h = __float2bfloat16(v);
        __nv_bfloat16 l = __float2bfloat16(v - __bfloat162float(h));
        g_Bimg[m * IMG_ELEMS + k * PK + n] = h;
        g_Bimg[m * IMG_ELEMS + IMG_HALF + k * PK + n] = l;
    } else if (idx < 12 * 16384 + 512) {
        int j = idx - 12 * 16384;
        g_emb[j] = sinf(t[0] * fw[j] + fb[j]);
    }
}

// ---------------- PTX helpers ----------------
__device__ __forceinline__ uint32_t smem_u32(const void* p) {
    uint32_t a;
    asm("{ .reg .u64 t; cvta.to.shared.u64 t, %1; cvt.u32.u64 %0, t; }" : "=r"(a) : "l"(p));
    return a;
}
__device__ __forceinline__ void ldsm4t(uint32_t r[4], uint32_t addr) {
    asm volatile("ldmatrix.sync.aligned.m8n8.x4.trans.shared.b16 {%0,%1,%2,%3}, [%4];"
                 : "=r"(r[0]), "=r"(r[1]), "=r"(r[2]), "=r"(r[3]) : "r"(addr));
}
__device__ __forceinline__ void mma16816(float c[4], const uint32_t a[4],
                                         uint32_t b0, uint32_t b1) {
    asm volatile("mma.sync.aligned.m16n8k16.row.col.f32.bf16.bf16.f32 "
                 "{%0,%1,%2,%3},{%4,%5,%6,%7},{%8,%9},{%0,%1,%2,%3};"
                 : "+f"(c[0]), "+f"(c[1]), "+f"(c[2]), "+f"(c[3])
                 : "r"(a[0]), "r"(a[1]), "r"(a[2]), "r"(a[3]), "r"(b0), "r"(b1));
}
// pack {x,y} -> bf16x2 hi + residual bf16x2 lo  (lo half of reg = x)
__device__ __forceinline__ void pack2(float x, float y, uint32_t& hi, uint32_t& lo) {
    asm("cvt.rn.bf16x2.f32 %0, %1, %2;" : "=r"(hi) : "f"(y), "f"(x));
    float hx = __uint_as_float(hi << 16);
    float hy = __uint_as_float(hi & 0xffff0000u);
    asm("cvt.rn.bf16x2.f32 %0, %1, %2;" : "=r"(lo) : "f"(y - hy), "f"(x - hx));
}
__device__ __forceinline__ float qreduce(float v) {   // sum over quad (lanes xor 1,2)
    v += __shfl_xor_sync(0xffffffffu, v, 1);
    v += __shfl_xor_sync(0xffffffffu, v, 2);
    return v;
}
__device__ __forceinline__ float softplusf_(float u) {
    return fmaxf(u, 0.f) + __logf(1.f + __expf(-fabsf(u)));
}
__device__ __forceinline__ int mat_for(int g) {
    return (g <= 6) ? g : (g == 11 ? 11 : 17 - g);
}

// async 69632B copy global -> smem (all 256 threads), one commit group
__device__ __forceinline__ void copyB_async(uint32_t dst, const __nv_bfloat16* src, int tid) {
    const char* s = (const char*)src + tid * 16;
    uint32_t d = dst + tid * 16;
#pragma unroll
    for (int it = 0; it < 17; it++)
        asm volatile("cp.async.cg.shared.global [%0], [%1], 16;"
                     :: "r"(d + it * 4096), "l"(s + it * 4096));
    asm volatile("cp.async.commit_group;" ::: "memory");
}

// ---------------- main kernel ----------------
extern __shared__ __align__(16) char smem[];

__global__ void __launch_bounds__(THREADS)
clnf_main(const float* __restrict__ p, const float* __restrict__ w,
          const float* __restrict__ b_in, const float* __restrict__ gamma,
          const float* __restrict__ beta, const float* __restrict__ bl,
          const float* __restrict__ b_out, float* __restrict__ out) {
    const int tid  = threadIdx.x;
    const int warp = tid >> 5, lane = tid & 31;
    const int qr   = lane >> 2, qc = lane & 3;
    const int rwA  = warp * 16 + qr;          // fragment row (rb=0)
    const int rwB  = rwA + 8;                 // fragment row (rb=1)
    const int colb = qc * 2;                  // thread col base within n-octet

    const uint32_t sbase = smem_u32(smem);
    float* cb   = (float*)(smem + SM_CB);
    float* cemb = (float*)(smem + SM_CEMB);
    float* cgam = (float*)(smem + SM_CGAM);
    float* cbet = (float*)(smem + SM_CBET);
    float* dwo  = out + (size_t)Bsz * 128;

    // consts -> SMEM
    if (tid < 128) { cb[tid] = b_in[tid]; cb[640 + tid] = b_out[tid]; }
#pragma unroll
    for (int i = 0; i < 2; i++) {
        int j = tid + i * 256;
        cb[128 + j] = bl[j];
        cemb[j] = g_emb[j];
        cgam[j] = gamma[j];
        cbet[j] = beta[j];
    }
    // preload B image 0 into buf0
    copyB_async(sbase + SM_B0, g_Bimg, tid);
    asm volatile("cp.async.wait_group 0;" ::: "memory");
    __syncthreads();

    // per-lane B base: lanes 0-15 -> hi image rows, lanes 16-31 -> lo image rows
    const uint32_t lane_b = (uint32_t)(lane & 15) * PKB + (uint32_t)(lane >> 4) * IMG_HALF_B;

    float mus[4][2], rss[4][2];
    float acc[16][4];

    for (int tile = blockIdx.x; tile < NTILES; tile += NBLK) {
        const size_t row0 = (size_t)tile * TR;

        // ---- initial A = p rows, straight into C-fragment registers ----
        {
            const float* pA = p + (row0 + rwA) * 128 + colb;
            const float* pB = p + (row0 + rwB) * 128 + colb;
#pragma unroll
            for (int nt = 0; nt < 16; nt++) {
                float2 va = *(const float2*)(pA + nt * 8);
                float2 vb = *(const float2*)(pB + nt * 8);
                acc[nt][0] = va.x; acc[nt][1] = va.y;
                acc[nt][2] = vb.x; acc[nt][3] = vb.y;
            }
        }

        for (int g = 0; g < 12; g++) {
            // prefetch next weight image (other buffer); consumed after barrier
            {
                int gn = (g == 11) ? 0 : g + 1;
                copyB_async(sbase + ((g & 1) ? SM_B0 : SM_B1),
                            g_Bimg + (size_t)mat_for(gn) * IMG_ELEMS, tid);
            }

            // ---- convert previous activations (C frags) -> A frags, in registers ----
            uint32_t aH[8][4], aL[8][4];
#pragma unroll
            for (int ks = 0; ks < 8; ks++) {
                pack2(acc[2*ks][0],   acc[2*ks][1],   aH[ks][0], aL[ks][0]);
                pack2(acc[2*ks][2],   acc[2*ks][3],   aH[ks][1], aL[ks][1]);
                pack2(acc[2*ks+1][0], acc[2*ks+1][1], aH[ks][2], aL[ks][2]);
                pack2(acc[2*ks+1][2], acc[2*ks+1][3], aH[ks][3], aL[ks][3]);
            }
#pragma unroll
            for (int nt = 0; nt < 16; nt++)
#pragma unroll
                for (int q = 0; q < 4; q++) acc[nt][q] = 0.f;

            // ---- GEMM: acc += Ah*Bh + Al*Bh + Ah*Bl ----
            {
                const uint32_t bbase = sbase + ((g & 1) ? SM_B1 : SM_B0) + lane_b;
#pragma unroll
                for (int ks = 0; ks < 8; ks++) {
                    const uint32_t krow = bbase + (uint32_t)(ks * 16) * PKB;
#pragma unroll
                    for (int nt = 0; nt < 16; nt++) {
                        uint32_t bf[4];                  // bh0,bh1,bl0,bl1
                        ldsm4t(bf, krow + nt * 16);
                        mma16816(acc[nt], aH[ks], bf[0], bf[1]);
                        mma16816(acc[nt], aL[ks], bf[0], bf[1]);
                        mma16816(acc[nt], aH[ks], bf[2], bf[3]);
                    }
                }
            }

            // ---- epilogue (warp-local, fragments stay in registers) ----
            if (g <= 4) {                      // + bias (b_in, bl0..3)
                const float* bp = cb + g * 128 + colb;
#pragma unroll
                for (int nt = 0; nt < 16; nt++) {
                    float2 b2 = *(const float2*)(bp + nt * 8);
                    acc[nt][0] += b2.x; acc[nt][1] += b2.y;
                    acc[nt][2] += b2.x; acc[nt][3] += b2.y;
                }
            }
            if (g <= 3) {                      // fwd layer g: emb, softplus, LN
                const float* eb = cemb + g * 128 + colb;
                const float* ga = cgam + g * 128 + colb;
                const float* be = cbet + g * 128 + colb;
#pragma unroll
                for (int rb = 0; rb < 2; rb++) {
                    int rw = rb ? rwB : rwA;
                    float sum = 0.f;
#pragma unroll
                    for (int nt = 0; nt < 16; nt++) {
                        float2 e2 = *(const float2*)(eb + nt * 8);
                        float s0 = softplusf_(acc[nt][2*rb]   + e2.x);
                        float s1 = softplusf_(acc[nt][2*rb+1] + e2.y);
                        acc[nt][2*rb] = s0; acc[nt][2*rb+1] = s1;
                        sum += s0 + s1;
                    }
                    float mu = qreduce(sum) * (1.f / 128.f);
                    float ssq = 0.f;
#pragma unroll
                    for (int nt = 0; nt < 16; nt++) {
                        float d0 = acc[nt][2*rb] - mu, d1 = acc[nt][2*rb+1] - mu;
                        ssq += d0 * d0 + d1 * d1;
                    }
                    float rs = rsqrtf(qreduce(ssq) * (1.f / 128.f) + LN_EPS);
                    mus[g][rb] = mu; rss[g][rb] = rs;
                    float* sp = g_s + (((size_t)blockIdx.x * 4 + g) * 128 + rw) * 128 + colb;
#pragma unroll
                    for (int nt = 0; nt < 16; nt++)
                        *(float2*)(sp + nt * 8) =
                            make_float2(acc[nt][2*rb], acc[nt][2*rb+1]);
#pragma unroll
                    for (int nt = 0; nt < 16; nt++) {
                        float2 g2 = *(const float2*)(ga + nt * 8);
                        float2 t2 = *(const float2*)(be + nt * 8);
                        acc[nt][2*rb]   = (acc[nt][2*rb]   - mu) * rs * g2.x + t2.x;
                        acc[nt][2*rb+1] = (acc[nt][2*rb+1] - mu) * rs * g2.y + t2.y;
                    }
                }
            } else if (g == 5) {               // dp out (+b_out); load w rows into acc
                const float* bp = cb + 640 + colb;
#pragma unroll
                for (int rb = 0; rb < 2; rb++) {
                    int rw = rb ? rwB : rwA;
                    float* dst = out + (row0 + rw) * 128 + colb;
#pragma unroll
                    for (int nt = 0; nt < 16; nt++) {
                        float2 b2 = *(const float2*)(bp + nt * 8);
                        *(float2*)(dst + nt * 8) =
                            make_float2(acc[nt][2*rb] + b2.x, acc[nt][2*rb+1] + b2.y);
                    }
                    const float* src = w + (row0 + rw) * 128 + colb;
#pragma unroll
                    for (int nt = 0; nt < 16; nt++) {
                        float2 v = *(const float2*)(src + nt * 8);
                        acc[nt][2*rb] = v.x; acc[nt][2*rb+1] = v.y;
                    }
                }
            } else if (g >= 7 && g <= 10) {    // bwd layer l = 10-g
                int l = 10 - g;
                const float* ga = cgam + l * 128 + colb;
#pragma unroll
                for (int rb = 0; rb < 2; rb++) {
                    int rw = rb ? rwB : rwA;
                    float mu = mus[l][rb], rs = rss[l][rb];
                    const float* sp = g_s +
                        (((size_t)blockIdx.x * 4 + l) * 128 + rw) * 128 + colb;
                    float sv[32];
#pragma unroll
                    for (int nt = 0; nt < 16; nt++) {
                        float2 s2 = *(const float2*)(sp + nt * 8);
                        sv[2*nt] = s2.x; sv[2*nt+1] = s2.y;
                    }
                    float m1 = 0.f, m2 = 0.f;
#pragma unroll
                    for (int nt = 0; nt < 16; nt++) {
                        float2 g2 = *(const float2*)(ga + nt * 8);
                        float t0 = acc[nt][2*rb]   * g2.x;
                        float t1 = acc[nt][2*rb+1] * g2.y;
                        m1 += t0 + t1;
                        m2 += t0 * ((sv[2*nt]   - mu) * rs) +
                              t1 * ((sv[2*nt+1] - mu) * rs);
                    }
                    m1 = qreduce(m1) * (1.f / 128.f);
                    m2 = qreduce(m2) * (1.f / 128.f);
#pragma unroll
                    for (int nt = 0; nt < 16; nt++) {
                        float2 g2 = *(const float2*)(ga + nt * 8);
                        float t0 = acc[nt][2*rb]   * g2.x;
                        float t1 = acc[nt][2*rb+1] * g2.y;
                        float x0 = (sv[2*nt]   - mu) * rs;
                        float x1 = (sv[2*nt+1] - mu) * rs;
                        acc[nt][2*rb]   = rs * (t0 - m1 - x0 * m2) * (1.f - __expf(-sv[2*nt]));
                        acc[nt][2*rb+1] = rs * (t1 - m1 - x1 * m2) * (1.f - __expf(-sv[2*nt+1]));
                    }
                }
            } else if (g == 11) {              // dw = -D
#pragma unroll
                for (int rb = 0; rb < 2; rb++) {
                    int rw = rb ? rwB : rwA;
                    float* dst = dwo + (row0 + rw) * 128 + colb;
#pragma unroll
                    for (int nt = 0; nt < 16; nt++)
                        *(float2*)(dst + nt * 8) =
                            make_float2(-acc[nt][2*rb], -acc[nt][2*rb+1]);
                }
            }
            // (g == 4 and g == 6 need nothing beyond the shared bias path)

            asm volatile("cp.async.wait_group 0;" ::: "memory");
            __syncthreads();   // B double-buffer handoff
        }
    }
}

// ---------------- launch ----------------
extern "C" void kernel_launch(void* const* d_in, const int* in_sizes, int n_in,
                              void* d_out, int out_size) {
    const float* t     = (const float*)d_in[0];
    const float* p     = (const float*)d_in[1];
    const float* w     = (const float*)d_in[2];
    const float* W_in  = (const float*)d_in[3];
    const float* b_in  = (const float*)d_in[4];
    const float* fw    = (const float*)d_in[5];
    const float* fb    = (const float*)d_in[6];
    const float* gamma = (const float*)d_in[7];
    const float* beta  = (const float*)d_in[8];
    const float* Wl    = (const float*)d_in[9];
    const float* bl    = (const float*)d_in[10];
    const float* W_out = (const float*)d_in[11];
    const float* b_out = (const float*)d_in[12];
    float* out = (float*)d_out;

    cudaFuncSetAttribute(clnf_main, cudaFuncAttributeMaxDynamicSharedMemorySize,
                         SM_TOTAL);

    int prep_total = 12 * 16384 + 512;
    prep_kernel<<<(prep_total + 255) / 256, 256>>>(t, W_in, fw, fb, Wl, W_out);
    clnf_main<<<NBLK, THREADS, SM_TOTAL>>>(p, w, b_in, gamma, beta, bl, b_out, out);
}